// round 13
// baseline (speedup 1.0000x reference)
#include <cuda_runtime.h>
#include <cstdint>

// Problem constants (fixed by reference setup_inputs).
constexpr int N_MOLS      = 2000;
constexpr int N_PER_MOL   = 64;
constexpr int PAIRS_PER_M = N_PER_MOL * (N_PER_MOL - 1);   // 4032 = 126 * 32
constexpr int UNITS_PER_M = PAIRS_PER_M / 32;              // 126
constexpr int TOTAL_UNITS = N_MOLS * UNITS_PER_M;          // 252000 units of 32 pairs
constexpr int GRID        = 1184;                          // 148 SMs x 8 blocks: ONE wave
constexpr int UNITS_BASE  = TOTAL_UNITS / GRID;            // 212
constexpr int UNITS_REM   = TOTAL_UNITS % GRID;            // 992 blocks get one extra
constexpr float CUT2      = 25.0f;                         // 5.0^2

// Output layout (flatten of reference tuple, all float32):
//   [0,    P)  : i_idx
//   [P,   2P)  : j_idx
//   [2P,  3P)  : d_ij
//   [3P,  6P)  : r_ij (row-major [P,3])
// with P = N_MOLS * PAIRS_PER_M = 8,064,000.

__global__ __launch_bounds__(256, 8)
void neighborlist_kernel(const float* __restrict__ pos, float* __restrict__ out)
{
    // A block's unit range spans at most 3 molecules (213 units < 2*126 + boundary).
    __shared__ float sx[3 * N_PER_MOL];
    __shared__ float sy[3 * N_PER_MOL];
    __shared__ float sz[3 * N_PER_MOL];

    const int bid  = blockIdx.x;
    const int t    = threadIdx.x;
    const int warp = t >> 5;
    const int lane = t & 31;

    // Balanced unit range: first UNITS_REM blocks take UNITS_BASE+1 units.
    const unsigned u_start = (unsigned)bid * UNITS_BASE + (unsigned)min(bid, UNITS_REM);
    const unsigned u_end   = u_start + UNITS_BASE + (bid < UNITS_REM ? 1u : 0u);

    const unsigned m_base = u_start / UNITS_PER_M;

    // Preload the (up to) 3 molecules this block touches: 192 atoms.
    if (t < 3 * N_PER_MOL) {
        const unsigned mm = m_base + (unsigned)(t >> 6);
        if (mm < (unsigned)N_MOLS) {
            const float* p = pos + (mm * N_PER_MOL + (unsigned)(t & 63)) * 3u;
            sx[t] = p[0];
            sy[t] = p[1];
            sz[t] = p[2];
        }
    }
    __syncthreads();

    const unsigned P = (unsigned)N_MOLS * PAIRS_PER_M;
    float* __restrict__ out_i = out;
    float* __restrict__ out_j = out + P;
    float* __restrict__ out_d = out + 2u * P;
    float* __restrict__ out_r = out + 3u * P;

    // Each warp consumes one 32-pair unit per pass. 4032 = 126*32 means every
    // unit lies entirely inside one molecule, and unit boundaries keep the
    // i/j/d stores 128B-line aligned and the r block 384B aligned.
    for (unsigned u = u_start + (unsigned)warp; u < u_end; u += 8) {
        const unsigned m  = u / UNITS_PER_M;               // const-div
        const unsigned lq = (u - m * UNITS_PER_M) * 32u + (unsigned)lane; // local pair
        const int i  = (int)(lq / 63u);                    // const-div
        const int jr = (int)lq - i * 63;
        const int j  = jr + (jr >= i ? 1 : 0);

        const int sb = (int)(m - m_base) * N_PER_MOL;
        const float dx = sx[sb + j] - sx[sb + i];
        const float dy = sy[sb + j] - sy[sb + i];
        const float dz = sz[sb + j] - sz[sb + i];
        const float q  = fmaf(dx, dx, fmaf(dy, dy, dz * dz));
        const bool  in_cut = (q <= CUT2);

        const float fabase = (float)(m * N_PER_MOL);
        const unsigned g = u * 32u + (unsigned)lane;       // global pair index

        __stcs(out_i + g, fabase + (float)i);
        __stcs(out_j + g, fabase + (float)j);
        __stcs(out_d + g, in_cut ? sqrtf(q) : 0.0f);

        float* __restrict__ r = out_r + 3u * g;
        __stcs(r + 0, in_cut ? dx : 0.0f);
        __stcs(r + 1, in_cut ? dy : 0.0f);
        __stcs(r + 2, in_cut ? dz : 0.0f);
    }
}

extern "C" void kernel_launch(void* const* d_in, const int* in_sizes, int n_in,
                              void* d_out, int out_size)
{
    const float* pos = (const float*)d_in[0];
    float* out = (float*)d_out;
    neighborlist_kernel<<<GRID, 256>>>(pos, out);
}

// round 14
// speedup vs baseline: 1.0581x; 1.0581x over previous
#include <cuda_runtime.h>
#include <cstdint>

// Problem constants (fixed by reference setup_inputs).
constexpr int N_MOLS      = 2000;
constexpr int N_PER_MOL   = 64;
constexpr int PAIRS_PER_M = N_PER_MOL * (N_PER_MOL - 1);   // 4032
constexpr float CUT2      = 25.0f;                         // 5.0^2

// Output layout (flatten of reference tuple, all float32):
//   [0,    P)  : i_idx
//   [P,   2P)  : j_idx
//   [2P,  3P)  : d_ij
//   [3P,  6P)  : r_ij (row-major [P,3])
// with P = N_MOLS * PAIRS_PER_M = 8,064,000.

__global__ __launch_bounds__(256)
void neighborlist_kernel(const float* __restrict__ pos, float* __restrict__ out)
{
    __shared__ float sx[N_PER_MOL];
    __shared__ float sy[N_PER_MOL];
    __shared__ float sz[N_PER_MOL];

    const int m = blockIdx.x;
    const int t = threadIdx.x;

    if (t < N_PER_MOL) {
        const float* p = pos + (unsigned)(m * N_PER_MOL + t) * 3u;
        sx[t] = p[0];
        sy[t] = p[1];
        sz[t] = p[2];
    }
    __syncthreads();

    const unsigned P = (unsigned)N_MOLS * PAIRS_PER_M;
    float* __restrict__ out_i = out;
    float* __restrict__ out_j = out + P;
    float* __restrict__ out_d = out + 2u * P;
    float* __restrict__ out_r = out + 3u * P;

    const unsigned base   = (unsigned)m * PAIRS_PER_M;
    const float    fabase = (float)(m * N_PER_MOL);

    // Decode thread's first pair once; then advance incrementally by 256
    // pairs per iteration (256 = 4*63 + 4 -> at most one wrap per step).
    int i  = t / 63;
    int jr = t - i * 63;

    for (int p = t; p < PAIRS_PER_M; p += 256) {
        const int j = jr + (jr >= i ? 1 : 0);

        const float dx = sx[j] - sx[i];
        const float dy = sy[j] - sy[i];
        const float dz = sz[j] - sz[i];
        const float q  = fmaf(dx, dx, fmaf(dy, dy, dz * dz));
        const bool  in_cut = (q <= CUT2);

        const unsigned g = base + (unsigned)p;

        // Write-through stores: output is write-once, never read, and larger
        // than L2 -- skip L2 allocation/dirty-line management entirely.
        __stwt(out_i + g, fabase + (float)i);
        __stwt(out_j + g, fabase + (float)j);
        __stwt(out_d + g, in_cut ? sqrtf(q) : 0.0f);

        float* __restrict__ r = out_r + 3u * g;
        __stwt(r + 0, in_cut ? dx : 0.0f);
        __stwt(r + 1, in_cut ? dy : 0.0f);
        __stwt(r + 2, in_cut ? dz : 0.0f);

        // Advance (i, jr) by 256 pairs: 256 = 4*63 + 4.
        jr += 4;
        const int w = (jr >= 63);
        jr -= w ? 63 : 0;
        i  += 4 + w;
    }
}

extern "C" void kernel_launch(void* const* d_in, const int* in_sizes, int n_in,
                              void* d_out, int out_size)
{
    const float* pos = (const float*)d_in[0];
    float* out = (float*)d_out;
    neighborlist_kernel<<<N_MOLS, 256>>>(pos, out);
}

// round 15
// speedup vs baseline: 1.0981x; 1.0378x over previous
#include <cuda_runtime.h>
#include <cstdint>

// Problem constants (fixed by reference setup_inputs).
constexpr int N_MOLS      = 2000;
constexpr int N_PER_MOL   = 64;
constexpr int PAIRS_PER_M = N_PER_MOL * (N_PER_MOL - 1);   // 4032
constexpr int HALF        = PAIRS_PER_M / 2;               // 2016 = 63*32 (warp-aligned)
constexpr float CUT2      = 25.0f;                         // 5.0^2

// Output layout (flatten of reference tuple, all float32):
//   [0,    P)  : i_idx
//   [P,   2P)  : j_idx
//   [2P,  3P)  : d_ij
//   [3P,  6P)  : r_ij (row-major [P,3])
// with P = N_MOLS * PAIRS_PER_M = 8,064,000.

__global__ __launch_bounds__(256)
void neighborlist_kernel(const float* __restrict__ pos, float* __restrict__ out)
{
    __shared__ float sx[N_PER_MOL];
    __shared__ float sy[N_PER_MOL];
    __shared__ float sz[N_PER_MOL];

    // Two blocks per molecule: finer scheduling quanta, same store geometry.
    const int m    = blockIdx.x >> 1;
    const int half = blockIdx.x & 1;
    const int t    = threadIdx.x;

    if (t < N_PER_MOL) {
        const float* p = pos + (unsigned)(m * N_PER_MOL + t) * 3u;
        sx[t] = p[0];
        sy[t] = p[1];
        sz[t] = p[2];
    }
    __syncthreads();

    const unsigned P = (unsigned)N_MOLS * PAIRS_PER_M;
    float* __restrict__ out_i = out;
    float* __restrict__ out_j = out + P;
    float* __restrict__ out_d = out + 2u * P;
    float* __restrict__ out_r = out + 3u * P;

    const unsigned base   = (unsigned)m * PAIRS_PER_M;
    const float    fabase = (float)(m * N_PER_MOL);

    const int p_begin = half * HALF;          // 0 or 2016
    const int p_end   = p_begin + HALF;

    // Decode this thread's first pair once, then advance by 256 per pass
    // (256 = 4*63 + 4 -> at most one wrap per step).
    const int p0 = p_begin + t;
    int i  = p0 / 63;
    int jr = p0 - i * 63;

    for (int p = p0; p < p_end; p += 256) {
        const int j = jr + (jr >= i ? 1 : 0);

        const float dx = sx[j] - sx[i];
        const float dy = sy[j] - sy[i];
        const float dz = sz[j] - sz[i];
        const float q  = fmaf(dx, dx, fmaf(dy, dy, dz * dz));
        const bool  in_cut = (q <= CUT2);

        const unsigned g = base + (unsigned)p;

        // Write-through stores: output is write-once, never read, larger
        // than L2 -- skip L2 allocation/dirty-line management.
        __stwt(out_i + g, fabase + (float)i);
        __stwt(out_j + g, fabase + (float)j);
        __stwt(out_d + g, in_cut ? sqrtf(q) : 0.0f);

        float* __restrict__ r = out_r + 3u * g;
        __stwt(r + 0, in_cut ? dx : 0.0f);
        __stwt(r + 1, in_cut ? dy : 0.0f);
        __stwt(r + 2, in_cut ? dz : 0.0f);

        // Advance (i, jr) by 256 pairs: 256 = 4*63 + 4.
        jr += 4;
        const int w = (jr >= 63);
        jr -= w ? 63 : 0;
        i  += 4 + w;
    }
}

extern "C" void kernel_launch(void* const* d_in, const int* in_sizes, int n_in,
                              void* d_out, int out_size)
{
    const float* pos = (const float*)d_in[0];
    float* out = (float*)d_out;
    neighborlist_kernel<<<2 * N_MOLS, 256>>>(pos, out);
}